// round 1
// baseline (speedup 1.0000x reference)
#include <cuda_runtime.h>
#include <math.h>

#define B_   16
#define C_   256
#define CIN  256
#define H_   128
#define W_   128
#define HW   (H_*W_)
#define TOT  (B_*C_*HW)

// Scratch for q,k,v (static __device__ arrays: allocation-guard safe)
__device__ float g_q[TOT];
__device__ float g_k[TOT];
__device__ float g_v[TOT];

// ---------------------------------------------------------------------------
// Conv 3x3 SAME, NCHW. One block: 64 output channels x one full output row.
// grid = (4 co-groups, 128 h, 16 b), block = 256 threads.
// Thread tile: 4 co x 8 px.
// ---------------------------------------------------------------------------
__global__ __launch_bounds__(256) void conv3x3_kernel(
    const float* __restrict__ x,
    const float* __restrict__ Wt,
    const float* __restrict__ bias,
    float* __restrict__ out)
{
    __shared__ float xs[3 * 136];   // 3 rows, padded (cols -1..128 -> 130 used)
    __shared__ float ws[64 * 9];    // 64 co x 3x3 for current ci

    const int cg  = blockIdx.x;     // 0..3  (group of 64 co)
    const int h   = blockIdx.y;     // 0..127
    const int b   = blockIdx.z;     // 0..15
    const int tid = threadIdx.x;
    const int px_base = (tid & 15) * 8;   // 0,8,...,120
    const int co_sub  = tid >> 4;         // 0..15 -> 4 co each

    float acc[4][8];
    #pragma unroll
    for (int i = 0; i < 4; ++i)
        #pragma unroll
        for (int j = 0; j < 8; ++j) acc[i][j] = 0.f;

    const float* xb = x + (size_t)b * CIN * HW;

    for (int ci = 0; ci < CIN; ++ci) {
        // stage weights for this ci: 64 co x 9 (L2-resident)
        for (int idx = tid; idx < 64 * 9; idx += 256) {
            int co_l = idx / 9;
            int k    = idx - co_l * 9;
            ws[idx] = Wt[(size_t)(cg * 64 + co_l) * (CIN * 9) + ci * 9 + k];
        }
        // stage 3 input rows (h-1, h, h+1), cols -1..128 with zero pad
        const float* xc = xb + (size_t)ci * HW;
        for (int idx = tid; idx < 3 * 130; idx += 256) {
            int r = idx / 130;
            int c = idx - r * 130;
            int hs = h + r - 1;
            int wsrc = c - 1;
            float v = 0.f;
            if (hs >= 0 && hs < H_ && wsrc >= 0 && wsrc < W_)
                v = xc[hs * W_ + wsrc];
            xs[r * 136 + c] = v;
        }
        __syncthreads();

        #pragma unroll
        for (int kh = 0; kh < 3; ++kh) {
            float xr[10];
            #pragma unroll
            for (int j = 0; j < 10; ++j)
                xr[j] = xs[kh * 136 + px_base + j];
            #pragma unroll
            for (int kw = 0; kw < 3; ++kw) {
                #pragma unroll
                for (int c4 = 0; c4 < 4; ++c4) {
                    float wv = ws[(co_sub * 4 + c4) * 9 + kh * 3 + kw];
                    #pragma unroll
                    for (int pj = 0; pj < 8; ++pj)
                        acc[c4][pj] += wv * xr[pj + kw];
                }
            }
        }
        __syncthreads();
    }

    #pragma unroll
    for (int c4 = 0; c4 < 4; ++c4) {
        int co = cg * 64 + co_sub * 4 + c4;
        float bb = bias[co];
        float* op = out + ((size_t)(b * C_ + co) * H_ + h) * W_ + px_base;
        #pragma unroll
        for (int pj = 0; pj < 8; ++pj) op[pj] = acc[c4][pj] + bb;
    }
}

// ---------------------------------------------------------------------------
// Row-attention per (b,c): scores = q k^T / sqrt(128), softmax over g,
// out = p v.  One block per (b,c), 256 threads (8 warps), K/V in smem.
// ---------------------------------------------------------------------------
#define PITCH 133   // odd -> conflict-free strided row access

__global__ __launch_bounds__(256) void attn_kernel(float* __restrict__ out)
{
    extern __shared__ float sm[];
    float* ks = sm;                      // 128 * PITCH
    float* vs = ks + 128 * PITCH;        // 128 * PITCH
    float* qs = vs + 128 * PITCH;        // 8 warps * 2 rows * 128
    float* ps = qs + 8 * 2 * 128;        // 8 warps * 2 rows * 128

    const int bc = blockIdx.x;           // b*256 + c
    const size_t base = (size_t)bc * HW;
    const int tid  = threadIdx.x;
    const int lane = tid & 31;
    const int warp = tid >> 5;

    for (int idx = tid; idx < HW; idx += 256) {
        int r = idx >> 7;
        int c = idx & 127;
        ks[r * PITCH + c] = g_k[base + idx];
        vs[r * PITCH + c] = g_v[base + idx];
    }
    __syncthreads();

    const float scale = rsqrtf(128.f);
    float* qw0 = qs + warp * 256;
    float* qw1 = qw0 + 128;
    float* pw0 = ps + warp * 256;
    float* pw1 = pw0 + 128;

    for (int it = 0; it < 8; ++it) {
        const int r0 = warp * 16 + it * 2;
        const int r1 = r0 + 1;

        #pragma unroll
        for (int i = 0; i < 4; ++i) {
            qw0[lane + 32 * i] = g_q[base + (size_t)r0 * 128 + lane + 32 * i];
            qw1[lane + 32 * i] = g_q[base + (size_t)r1 * 128 + lane + 32 * i];
        }
        __syncwarp();

        // scores: lane owns g = lane + 32*i
        float s0[4], s1[4];
        #pragma unroll
        for (int i = 0; i < 4; ++i) { s0[i] = 0.f; s1[i] = 0.f; }
        for (int w = 0; w < 128; ++w) {
            float q0 = qw0[w], q1 = qw1[w];
            #pragma unroll
            for (int i = 0; i < 4; ++i) {
                float kv = ks[(lane + 32 * i) * PITCH + w];
                s0[i] += q0 * kv;
                s1[i] += q1 * kv;
            }
        }

        // softmax over g (128 values spread 4-per-lane)
        float m0 = -1e30f, m1 = -1e30f;
        #pragma unroll
        for (int i = 0; i < 4; ++i) {
            s0[i] *= scale; s1[i] *= scale;
            m0 = fmaxf(m0, s0[i]); m1 = fmaxf(m1, s1[i]);
        }
        #pragma unroll
        for (int o = 16; o > 0; o >>= 1) {
            m0 = fmaxf(m0, __shfl_xor_sync(0xffffffffu, m0, o));
            m1 = fmaxf(m1, __shfl_xor_sync(0xffffffffu, m1, o));
        }
        float e0 = 0.f, e1 = 0.f;
        #pragma unroll
        for (int i = 0; i < 4; ++i) {
            s0[i] = __expf(s0[i] - m0); s1[i] = __expf(s1[i] - m1);
            e0 += s0[i]; e1 += s1[i];
        }
        #pragma unroll
        for (int o = 16; o > 0; o >>= 1) {
            e0 += __shfl_xor_sync(0xffffffffu, e0, o);
            e1 += __shfl_xor_sync(0xffffffffu, e1, o);
        }
        float i0 = 1.f / e0, i1 = 1.f / e1;
        #pragma unroll
        for (int i = 0; i < 4; ++i) {
            pw0[lane + 32 * i] = s0[i] * i0;
            pw1[lane + 32 * i] = s1[i] * i1;
        }
        __syncwarp();

        // out = p @ V : lane owns w = lane + 32*i
        float o0[4], o1[4];
        #pragma unroll
        for (int i = 0; i < 4; ++i) { o0[i] = 0.f; o1[i] = 0.f; }
        for (int g = 0; g < 128; ++g) {
            float p0 = pw0[g], p1 = pw1[g];
            #pragma unroll
            for (int i = 0; i < 4; ++i) {
                float vv = vs[g * PITCH + lane + 32 * i];
                o0[i] += p0 * vv;
                o1[i] += p1 * vv;
            }
        }
        float* op0 = out + base + (size_t)r0 * 128;
        float* op1 = op0 + 128;
        #pragma unroll
        for (int i = 0; i < 4; ++i) {
            op0[lane + 32 * i] = o0[i];
            op1[lane + 32 * i] = o1[i];
        }
        __syncwarp();   // protect qw/pw reuse next iteration
    }
}

// ---------------------------------------------------------------------------
extern "C" void kernel_launch(void* const* d_in, const int* in_sizes, int n_in,
                              void* d_out, int out_size)
{
    const float* x  = (const float*)d_in[0];
    const float* Wq = (const float*)d_in[1];
    const float* bq = (const float*)d_in[2];
    const float* Wk = (const float*)d_in[3];
    const float* bk = (const float*)d_in[4];
    const float* Wv = (const float*)d_in[5];
    const float* bv = (const float*)d_in[6];
    float* out = (float*)d_out;

    float *qp, *kp, *vp;
    cudaGetSymbolAddress((void**)&qp, g_q);
    cudaGetSymbolAddress((void**)&kp, g_k);
    cudaGetSymbolAddress((void**)&vp, g_v);

    const int attn_smem = (2 * 128 * PITCH + 2 * 8 * 2 * 128) * (int)sizeof(float);
    cudaFuncSetAttribute(attn_kernel, cudaFuncAttributeMaxDynamicSharedMemorySize, attn_smem);

    dim3 cgrid(4, 128, 16);
    conv3x3_kernel<<<cgrid, 256>>>(x, Wq, bq, qp);
    conv3x3_kernel<<<cgrid, 256>>>(x, Wk, bk, kp);
    conv3x3_kernel<<<cgrid, 256>>>(x, Wv, bv, vp);

    attn_kernel<<<B_ * C_, 256, attn_smem>>>(out);
}

// round 3
// speedup vs baseline: 4.7072x; 4.7072x over previous
#include <cuda_runtime.h>
#include <cstdint>
#include <math.h>

#define B_   16
#define C_   256
#define CIN  256
#define H_   128
#define W_   128
#define HW   (H_*W_)
#define TOT  ((size_t)B_*C_*HW)

// ---------------- device scratch (allocation-guard safe) -------------------
__device__ float    g_q[TOT];
__device__ float    g_k[TOT];
__device__ float    g_v[TOT];
__device__ uint32_t g_x32[(size_t)B_*CIN*HW];     // x as tf32 bits, NCHW
__device__ uint32_t g_wT[(size_t)3*9*256*256];    // [t][kk][ci][co] tf32 bits

// ---------------- helpers ---------------------------------------------------
__device__ __forceinline__ uint32_t smem_u32(const void* p) {
    uint32_t a;
    asm("{ .reg .u64 t; cvta.to.shared.u64 t, %1; cvt.u32.u64 %0, t; }" : "=r"(a) : "l"(p));
    return a;
}
__device__ __forceinline__ uint32_t f2tf(float f) {
    uint32_t r; asm("cvt.rna.tf32.f32 %0, %1;" : "=r"(r) : "f"(f)); return r;
}
__device__ __forceinline__ void cpa16(uint32_t d, const void* s) {
    asm volatile("cp.async.cg.shared.global [%0], [%1], 16;" :: "r"(d), "l"(s));
}
__device__ __forceinline__ void cpa4z(uint32_t d, const void* s, int sz) {
    asm volatile("cp.async.ca.shared.global [%0], [%1], 4, %2;" :: "r"(d), "l"(s), "r"(sz));
}
#define CP_COMMIT() asm volatile("cp.async.commit_group;" ::: "memory")
#define CP_WAIT1()  asm volatile("cp.async.wait_group 1;" ::: "memory")

__device__ __forceinline__ void mma8(float* c, const uint32_t* a, const uint32_t* b) {
    asm volatile(
        "mma.sync.aligned.m16n8k8.row.col.f32.tf32.tf32.f32 "
        "{%0,%1,%2,%3}, {%4,%5,%6,%7}, {%8,%9}, {%0,%1,%2,%3};"
        : "+f"(c[0]), "+f"(c[1]), "+f"(c[2]), "+f"(c[3])
        : "r"(a[0]), "r"(a[1]), "r"(a[2]), "r"(a[3]), "r"(b[0]), "r"(b[1]));
}

// ---------------- prologue: convert x and W to tf32 bits --------------------
__global__ __launch_bounds__(512) void xcvt_kernel(const float4* __restrict__ x) {
    const size_t N4 = (size_t)B_ * CIN * HW / 4;
    uint4* dst = (uint4*)g_x32;
    for (size_t i = (size_t)blockIdx.x * blockDim.x + threadIdx.x; i < N4;
         i += (size_t)gridDim.x * blockDim.x) {
        float4 v = x[i];
        uint4 o;
        o.x = f2tf(v.x); o.y = f2tf(v.y); o.z = f2tf(v.z); o.w = f2tf(v.w);
        dst[i] = o;
    }
}

// W [co][ci][3][3] -> g_wT [t][kk][ci][co], tf32
__global__ __launch_bounds__(256) void wcvt_kernel(
    const float* __restrict__ Wq, const float* __restrict__ Wk, const float* __restrict__ Wv) {
    __shared__ float s[2304];
    const int co = blockIdx.x, t = blockIdx.y;
    const float* src = ((t == 0) ? Wq : (t == 1) ? Wk : Wv) + (size_t)co * 2304;
    for (int i = threadIdx.x; i < 2304; i += 256) s[i] = src[i];
    __syncthreads();
    const int ci = threadIdx.x;
    uint32_t* dst = g_wT + (size_t)t * 9 * 65536;
    #pragma unroll
    for (int kk = 0; kk < 9; ++kk)
        dst[((size_t)kk * 256 + ci) * 256 + co] = f2tf(s[ci * 9 + kk]);
}

// ---------------- conv: implicit GEMM on mma.sync tf32 ----------------------
// grid (2048 bh, 3 tensor), 512 threads. CTA tile M=256 co x N=128 px.
// 3-stage cp.async pipeline; chunk = 32 K (one (kh,kw,ci-block)).
#define SA_STRIDE 264
#define SB_STRIDE 136
#define SA_WORDS  (32 * SA_STRIDE)          // 8448
#define SB_WORDS  (32 * SB_STRIDE)          // 4352
#define SB_BASE   (3 * SA_WORDS)            // 25344
#define CONV_SMEM ((3 * SA_WORDS + 3 * SB_WORDS) * 4)   // 153600 B

__global__ __launch_bounds__(512, 1) void conv_kernel(
    const float* __restrict__ bq, const float* __restrict__ bk, const float* __restrict__ bv) {
    extern __shared__ uint32_t sm[];
    const int tid = threadIdx.x, lane = tid & 31, warp = tid >> 5;
    const int gid = lane >> 2, tig = lane & 3;
    const int cob = (warp >> 2) * 64, nb = (warp & 3) * 32;
    const int bh = blockIdx.x, t = blockIdx.y;
    const int b = bh >> 7, h = bh & 127;
    const int kh0 = (h == 0) ? 1 : 0;
    const int kh1 = (h == 127) ? 1 : 2;
    const int nch = (kh1 - kh0 + 1) * 24;
    const uint32_t smbase = smem_u32(sm);

    float acc[4][4][4];
    #pragma unroll
    for (int i = 0; i < 4; ++i)
        #pragma unroll
        for (int j = 0; j < 4; ++j)
            #pragma unroll
            for (int l = 0; l < 4; ++l) acc[i][j][l] = 0.f;

    auto fill = [&](int it) {
        const int kh = kh0 + it / 24;
        const int rem = it % 24;
        const int kw = rem >> 3, c8 = rem & 7;
        const int hsrc = h + kh - 1;
        const int s = it % 3;
        // A: weights [kk][ci-chunk][co], 4 x 16B per thread
        const uint32_t* wp = g_wT + (((size_t)t * 9 + kh * 3 + kw) * 256 + c8 * 32) * 256;
        const uint32_t dA = smbase + (s * SA_WORDS) * 4;
        #pragma unroll
        for (int i = 0; i < 4; ++i) {
            const int idx = tid + i * 512;
            const int k = idx >> 6, co4 = (idx & 63) << 2;
            cpa16(dA + (uint32_t)(k * SA_STRIDE + co4) * 4, wp + k * 256 + co4);
        }
        // B: x row (shifted by kw), 8 x 4B per thread, zero-fill halo
        const uint32_t* xp = g_x32 + (((size_t)b * 256 + c8 * 32) * 128 + hsrc) * 128;
        const uint32_t dB = smbase + (SB_BASE + s * SB_WORDS) * 4;
        #pragma unroll
        for (int i = 0; i < 8; ++i) {
            const int idx = tid + i * 512;
            const int k = idx >> 7, nn = idx & 127;
            const int wsrc = nn + kw - 1;
            const int sz = ((unsigned)wsrc < 128u) ? 4 : 0;
            const int wc = min(max(wsrc, 0), 127);
            cpa4z(dB + (uint32_t)(k * SB_STRIDE + nn) * 4, xp + (size_t)k * HW + wc, sz);
        }
    };

    auto compute = [&](int s) {
        const uint32_t* A = sm + s * SA_WORDS;
        const uint32_t* Bp = sm + SB_BASE + s * SB_WORDS;
        #pragma unroll
        for (int ks = 0; ks < 4; ++ks) {
            const int k0 = ks * 8;
            uint32_t af[4][4], bf[4][2];
            #pragma unroll
            for (int mi = 0; mi < 4; ++mi) {
                const int base = (k0 + tig) * SA_STRIDE + cob + mi * 16 + gid;
                af[mi][0] = A[base];
                af[mi][1] = A[base + 8];
                af[mi][2] = A[base + 4 * SA_STRIDE];
                af[mi][3] = A[base + 4 * SA_STRIDE + 8];
            }
            #pragma unroll
            for (int ni = 0; ni < 4; ++ni) {
                const int base = (k0 + tig) * SB_STRIDE + nb + ni * 8 + gid;
                bf[ni][0] = Bp[base];
                bf[ni][1] = Bp[base + 4 * SB_STRIDE];
            }
            #pragma unroll
            for (int mi = 0; mi < 4; ++mi)
                #pragma unroll
                for (int ni = 0; ni < 4; ++ni)
                    mma8(acc[mi][ni], af[mi], bf[ni]);
        }
    };

    fill(0); CP_COMMIT();
    fill(1); CP_COMMIT();
    for (int it = 0; it < nch; ++it) {
        CP_WAIT1();
        __syncthreads();
        compute(it % 3);
        if (it + 2 < nch) fill(it + 2);
        CP_COMMIT();
    }

    // epilogue: bias + store
    float* outp = (t == 0) ? g_q : (t == 1) ? g_k : g_v;
    const float* bias = (t == 0) ? bq : (t == 1) ? bk : bv;
    #pragma unroll
    for (int mi = 0; mi < 4; ++mi) {
        const int co0 = cob + mi * 16 + gid;
        const float bv0 = bias[co0], bv1 = bias[co0 + 8];
        float* r0 = outp + (((size_t)b * C_ + co0) * H_ + h) * W_;
        float* r1 = r0 + (size_t)8 * HW;
        #pragma unroll
        for (int ni = 0; ni < 4; ++ni) {
            const int col = nb + ni * 8 + 2 * tig;
            float2 v0 = make_float2(acc[mi][ni][0] + bv0, acc[mi][ni][1] + bv0);
            float2 v1 = make_float2(acc[mi][ni][2] + bv1, acc[mi][ni][3] + bv1);
            *(float2*)(r0 + col) = v0;
            *(float2*)(r1 + col) = v1;
        }
    }
}

// ---------------- attention (unchanged, fp32) -------------------------------
#define PITCH 133

__global__ __launch_bounds__(256) void attn_kernel(float* __restrict__ out) {
    extern __shared__ float smf[];
    float* ks = smf;
    float* vs = ks + 128 * PITCH;
    float* qs = vs + 128 * PITCH;
    float* ps = qs + 8 * 2 * 128;

    const int bc = blockIdx.x;
    const size_t base = (size_t)bc * HW;
    const int tid = threadIdx.x;
    const int lane = tid & 31;
    const int warp = tid >> 5;

    for (int idx = tid; idx < HW; idx += 256) {
        int r = idx >> 7, c = idx & 127;
        ks[r * PITCH + c] = g_k[base + idx];
        vs[r * PITCH + c] = g_v[base + idx];
    }
    __syncthreads();

    const float scale = rsqrtf(128.f);
    float* qw0 = qs + warp * 256;  float* qw1 = qw0 + 128;
    float* pw0 = ps + warp * 256;  float* pw1 = pw0 + 128;

    for (int it = 0; it < 8; ++it) {
        const int r0 = warp * 16 + it * 2, r1 = r0 + 1;
        #pragma unroll
        for (int i = 0; i < 4; ++i) {
            qw0[lane + 32 * i] = g_q[base + (size_t)r0 * 128 + lane + 32 * i];
            qw1[lane + 32 * i] = g_q[base + (size_t)r1 * 128 + lane + 32 * i];
        }
        __syncwarp();

        float s0[4], s1[4];
        #pragma unroll
        for (int i = 0; i < 4; ++i) { s0[i] = 0.f; s1[i] = 0.f; }
        for (int w = 0; w < 128; ++w) {
            float q0 = qw0[w], q1 = qw1[w];
            #pragma unroll
            for (int i = 0; i < 4; ++i) {
                float kv = ks[(lane + 32 * i) * PITCH + w];
                s0[i] += q0 * kv;  s1[i] += q1 * kv;
            }
        }
        float m0 = -1e30f, m1 = -1e30f;
        #pragma unroll
        for (int i = 0; i < 4; ++i) {
            s0[i] *= scale; s1[i] *= scale;
            m0 = fmaxf(m0, s0[i]); m1 = fmaxf(m1, s1[i]);
        }
        #pragma unroll
        for (int o = 16; o > 0; o >>= 1) {
            m0 = fmaxf(m0, __shfl_xor_sync(0xffffffffu, m0, o));
            m1 = fmaxf(m1, __shfl_xor_sync(0xffffffffu, m1, o));
        }
        float e0 = 0.f, e1 = 0.f;
        #pragma unroll
        for (int i = 0; i < 4; ++i) {
            s0[i] = __expf(s0[i] - m0); s1[i] = __expf(s1[i] - m1);
            e0 += s0[i]; e1 += s1[i];
        }
        #pragma unroll
        for (int o = 16; o > 0; o >>= 1) {
            e0 += __shfl_xor_sync(0xffffffffu, e0, o);
            e1 += __shfl_xor_sync(0xffffffffu, e1, o);
        }
        float i0 = 1.f / e0, i1 = 1.f / e1;
        #pragma unroll
        for (int i = 0; i < 4; ++i) {
            pw0[lane + 32 * i] = s0[i] * i0;
            pw1[lane + 32 * i] = s1[i] * i1;
        }
        __syncwarp();

        float o0[4], o1[4];
        #pragma unroll
        for (int i = 0; i < 4; ++i) { o0[i] = 0.f; o1[i] = 0.f; }
        for (int g = 0; g < 128; ++g) {
            float p0 = pw0[g], p1 = pw1[g];
            #pragma unroll
            for (int i = 0; i < 4; ++i) {
                float vv = vs[g * PITCH + lane + 32 * i];
                o0[i] += p0 * vv;  o1[i] += p1 * vv;
            }
        }
        float* op0 = out + base + (size_t)r0 * 128;
        float* op1 = op0 + 128;
        #pragma unroll
        for (int i = 0; i < 4; ++i) {
            op0[lane + 32 * i] = o0[i];
            op1[lane + 32 * i] = o1[i];
        }
        __syncwarp();
    }
}

// ---------------------------------------------------------------------------
extern "C" void kernel_launch(void* const* d_in, const int* in_sizes, int n_in,
                              void* d_out, int out_size) {
    const float* x  = (const float*)d_in[0];
    const float* Wq = (const float*)d_in[1];
    const float* bq = (const float*)d_in[2];
    const float* Wk = (const float*)d_in[3];
    const float* bk = (const float*)d_in[4];
    const float* Wv = (const float*)d_in[5];
    const float* bv = (const float*)d_in[6];
    float* out = (float*)d_out;

    static bool attr_done = false;
    if (!attr_done) {
        cudaFuncSetAttribute(conv_kernel, cudaFuncAttributeMaxDynamicSharedMemorySize, CONV_SMEM);
        const int attn_smem = (2 * 128 * PITCH + 2 * 8 * 2 * 128) * (int)sizeof(float);
        cudaFuncSetAttribute(attn_kernel, cudaFuncAttributeMaxDynamicSharedMemorySize, attn_smem);
        attr_done = true;
    }

    xcvt_kernel<<<16384, 512>>>((const float4*)x);
    wcvt_kernel<<<dim3(256, 3), 256>>>(Wq, Wk, Wv);

    conv_kernel<<<dim3(B_ * H_, 3), 512, CONV_SMEM>>>(bq, bk, bv);

    const int attn_smem = (2 * 128 * PITCH + 2 * 8 * 2 * 128) * (int)sizeof(float);
    attn_kernel<<<B_ * C_, 256, attn_smem>>>(out);
}

// round 4
// speedup vs baseline: 6.1043x; 1.2968x over previous
#include <cuda_runtime.h>
#include <cstdint>
#include <math.h>

#define B_   16
#define C_   256
#define CIN  256
#define H_   128
#define W_   128
#define HW   (H_*W_)
#define TOT  ((size_t)B_*C_*HW)

// ---------------- device scratch (allocation-guard safe) -------------------
__device__ uint32_t g_q[TOT];                     // tf32 bits
__device__ uint32_t g_k[TOT];                     // tf32 bits
__device__ uint32_t g_v[TOT];                     // tf32 bits
__device__ uint32_t g_x32[(size_t)B_*CIN*HW];     // x as tf32 bits, NCHW
__device__ uint32_t g_wT[(size_t)3*9*256*256];    // [t][kk][ci][co] tf32 bits

// ---------------- helpers ---------------------------------------------------
__device__ __forceinline__ uint32_t smem_u32(const void* p) {
    uint32_t a;
    asm("{ .reg .u64 t; cvta.to.shared.u64 t, %1; cvt.u32.u64 %0, t; }" : "=r"(a) : "l"(p));
    return a;
}
__device__ __forceinline__ uint32_t f2tf(float f) {
    uint32_t r; asm("cvt.rna.tf32.f32 %0, %1;" : "=r"(r) : "f"(f)); return r;
}
__device__ __forceinline__ void cpa16(uint32_t d, const void* s) {
    asm volatile("cp.async.cg.shared.global [%0], [%1], 16;" :: "r"(d), "l"(s));
}
__device__ __forceinline__ void cpa4z(uint32_t d, const void* s, int sz) {
    asm volatile("cp.async.ca.shared.global [%0], [%1], 4, %2;" :: "r"(d), "l"(s), "r"(sz));
}
#define CP_COMMIT() asm volatile("cp.async.commit_group;" ::: "memory")
#define CP_WAIT1()  asm volatile("cp.async.wait_group 1;" ::: "memory")
#define CP_WAIT0()  asm volatile("cp.async.wait_group 0;" ::: "memory")

__device__ __forceinline__ void mma8(float* c, const uint32_t* a, const uint32_t* b) {
    asm volatile(
        "mma.sync.aligned.m16n8k8.row.col.f32.tf32.tf32.f32 "
        "{%0,%1,%2,%3}, {%4,%5,%6,%7}, {%8,%9}, {%0,%1,%2,%3};"
        : "+f"(c[0]), "+f"(c[1]), "+f"(c[2]), "+f"(c[3])
        : "r"(a[0]), "r"(a[1]), "r"(a[2]), "r"(a[3]), "r"(b[0]), "r"(b[1]));
}

// ---------------- prologue: convert x and W to tf32 bits --------------------
__global__ __launch_bounds__(512) void xcvt_kernel(const float4* __restrict__ x) {
    const size_t N4 = (size_t)B_ * CIN * HW / 4;
    uint4* dst = (uint4*)g_x32;
    for (size_t i = (size_t)blockIdx.x * blockDim.x + threadIdx.x; i < N4;
         i += (size_t)gridDim.x * blockDim.x) {
        float4 v = x[i];
        uint4 o;
        o.x = f2tf(v.x); o.y = f2tf(v.y); o.z = f2tf(v.z); o.w = f2tf(v.w);
        dst[i] = o;
    }
}

// W [co][ci][3][3] -> g_wT [t][kk][ci][co], tf32
__global__ __launch_bounds__(256) void wcvt_kernel(
    const float* __restrict__ Wq, const float* __restrict__ Wk, const float* __restrict__ Wv) {
    __shared__ float s[2304];
    const int co = blockIdx.x, t = blockIdx.y;
    const float* src = ((t == 0) ? Wq : (t == 1) ? Wk : Wv) + (size_t)co * 2304;
    for (int i = threadIdx.x; i < 2304; i += 256) s[i] = src[i];
    __syncthreads();
    const int ci = threadIdx.x;
    uint32_t* dst = g_wT + (size_t)t * 9 * 65536;
    #pragma unroll
    for (int kk = 0; kk < 9; ++kk)
        dst[((size_t)kk * 256 + ci) * 256 + co] = f2tf(s[ci * 9 + kk]);
}

// ---------------- conv: implicit GEMM on mma.sync tf32 ----------------------
#define SA_STRIDE 264
#define SB_STRIDE 136
#define SA_WORDS  (32 * SA_STRIDE)
#define SB_WORDS  (32 * SB_STRIDE)
#define SB_BASE   (3 * SA_WORDS)
#define CONV_SMEM ((3 * SA_WORDS + 3 * SB_WORDS) * 4)

__global__ __launch_bounds__(512, 1) void conv_kernel(
    const float* __restrict__ bq, const float* __restrict__ bk, const float* __restrict__ bv) {
    extern __shared__ uint32_t sm[];
    const int tid = threadIdx.x, lane = tid & 31, warp = tid >> 5;
    const int gid = lane >> 2, tig = lane & 3;
    const int cob = (warp >> 2) * 64, nb = (warp & 3) * 32;
    const int bh = blockIdx.x, t = blockIdx.y;
    const int b = bh >> 7, h = bh & 127;
    const int kh0 = (h == 0) ? 1 : 0;
    const int kh1 = (h == 127) ? 1 : 2;
    const int nch = (kh1 - kh0 + 1) * 24;
    const uint32_t smbase = smem_u32(sm);

    float acc[4][4][4];
    #pragma unroll
    for (int i = 0; i < 4; ++i)
        #pragma unroll
        for (int j = 0; j < 4; ++j)
            #pragma unroll
            for (int l = 0; l < 4; ++l) acc[i][j][l] = 0.f;

    auto fill = [&](int it) {
        const int kh = kh0 + it / 24;
        const int rem = it % 24;
        const int kw = rem >> 3, c8 = rem & 7;
        const int hsrc = h + kh - 1;
        const int s = it % 3;
        const uint32_t* wp = g_wT + (((size_t)t * 9 + kh * 3 + kw) * 256 + c8 * 32) * 256;
        const uint32_t dA = smbase + (s * SA_WORDS) * 4;
        #pragma unroll
        for (int i = 0; i < 4; ++i) {
            const int idx = tid + i * 512;
            const int k = idx >> 6, co4 = (idx & 63) << 2;
            cpa16(dA + (uint32_t)(k * SA_STRIDE + co4) * 4, wp + k * 256 + co4);
        }
        const uint32_t* xp = g_x32 + (((size_t)b * 256 + c8 * 32) * 128 + hsrc) * 128;
        const uint32_t dB = smbase + (SB_BASE + s * SB_WORDS) * 4;
        #pragma unroll
        for (int i = 0; i < 8; ++i) {
            const int idx = tid + i * 512;
            const int k = idx >> 7, nn = idx & 127;
            const int wsrc = nn + kw - 1;
            const int sz = ((unsigned)wsrc < 128u) ? 4 : 0;
            const int wc = min(max(wsrc, 0), 127);
            cpa4z(dB + (uint32_t)(k * SB_STRIDE + nn) * 4, xp + (size_t)k * HW + wc, sz);
        }
    };

    auto compute = [&](int s) {
        const uint32_t* A = sm + s * SA_WORDS;
        const uint32_t* Bp = sm + SB_BASE + s * SB_WORDS;
        #pragma unroll
        for (int ks = 0; ks < 4; ++ks) {
            const int k0 = ks * 8;
            uint32_t af[4][4], bf[4][2];
            #pragma unroll
            for (int mi = 0; mi < 4; ++mi) {
                const int base = (k0 + tig) * SA_STRIDE + cob + mi * 16 + gid;
                af[mi][0] = A[base];
                af[mi][1] = A[base + 8];
                af[mi][2] = A[base + 4 * SA_STRIDE];
                af[mi][3] = A[base + 4 * SA_STRIDE + 8];
            }
            #pragma unroll
            for (int ni = 0; ni < 4; ++ni) {
                const int base = (k0 + tig) * SB_STRIDE + nb + ni * 8 + gid;
                bf[ni][0] = Bp[base];
                bf[ni][1] = Bp[base + 4 * SB_STRIDE];
            }
            #pragma unroll
            for (int mi = 0; mi < 4; ++mi)
                #pragma unroll
                for (int ni = 0; ni < 4; ++ni)
                    mma8(acc[mi][ni], af[mi], bf[ni]);
        }
    };

    fill(0); CP_COMMIT();
    fill(1); CP_COMMIT();
    for (int it = 0; it < nch; ++it) {
        CP_WAIT1();
        __syncthreads();
        compute(it % 3);
        if (it + 2 < nch) fill(it + 2);
        CP_COMMIT();
    }

    // epilogue: bias + store as tf32 bits
    uint32_t* outp = (t == 0) ? g_q : (t == 1) ? g_k : g_v;
    const float* bias = (t == 0) ? bq : (t == 1) ? bk : bv;
    #pragma unroll
    for (int mi = 0; mi < 4; ++mi) {
        const int co0 = cob + mi * 16 + gid;
        const float bv0 = bias[co0], bv1 = bias[co0 + 8];
        uint32_t* r0 = outp + (((size_t)b * C_ + co0) * H_ + h) * W_;
        uint32_t* r1 = r0 + (size_t)8 * HW;
        #pragma unroll
        for (int ni = 0; ni < 4; ++ni) {
            const int col = nb + ni * 8 + 2 * tig;
            uint2 v0 = make_uint2(f2tf(acc[mi][ni][0] + bv0), f2tf(acc[mi][ni][1] + bv0));
            uint2 v1 = make_uint2(f2tf(acc[mi][ni][2] + bv1), f2tf(acc[mi][ni][3] + bv1));
            *(uint2*)(r0 + col) = v0;
            *(uint2*)(r1 + col) = v1;
        }
    }
}

// ---------------- attention: tensor-core tf32 -------------------------------
// One CTA per (b,c); 8 warps x 16 q-rows. Q/K/V staged in smem (pitch 132).
#define AP 132
#define ATTN_SMEM (3 * 128 * AP * 4)   // 202752 B

__global__ __launch_bounds__(256, 1) void attn_kernel(float* __restrict__ out) {
    extern __shared__ uint32_t asm_[];
    uint32_t* qs = asm_;
    uint32_t* ks = qs + 128 * AP;
    uint32_t* vs = ks + 128 * AP;

    const int bc = blockIdx.x;
    const size_t base = (size_t)bc * HW;
    const int tid = threadIdx.x;
    const int lane = tid & 31;
    const int warp = tid >> 5;
    const int gid = lane >> 2, tig = lane & 3;
    const uint32_t smbase = smem_u32(asm_);

    // stage Q, K, V (16B cp.async; pitch 132 keeps 16B dst alignment)
    for (int i = tid; i < 4096; i += 256) {
        const int r = i >> 5, c4 = i & 31;
        const uint32_t doff = (uint32_t)(r * AP + c4 * 4) * 4;
        const size_t goff = base + (size_t)r * 128 + c4 * 4;
        cpa16(smbase + doff,                       g_q + goff);
        cpa16(smbase + 128 * AP * 4 + doff,        g_k + goff);
        cpa16(smbase + 2 * 128 * AP * 4 + doff,    g_v + goff);
    }
    CP_COMMIT(); CP_WAIT0();
    __syncthreads();

    const uint32_t* qw = qs + warp * 16 * AP;   // warp's 16 q rows
    uint32_t* pw = qs + warp * 16 * AP;         // reused for P after S

    // ---- S = Q K^T ----
    float sacc[16][4];
    #pragma unroll
    for (int nt = 0; nt < 16; ++nt)
        #pragma unroll
        for (int j = 0; j < 4; ++j) sacc[nt][j] = 0.f;

    #pragma unroll
    for (int kt = 0; kt < 16; ++kt) {
        const int k0 = kt * 8;
        uint32_t a[4];
        a[0] = qw[gid * AP + k0 + tig];
        a[1] = qw[(gid + 8) * AP + k0 + tig];
        a[2] = qw[gid * AP + k0 + tig + 4];
        a[3] = qw[(gid + 8) * AP + k0 + tig + 4];
        #pragma unroll
        for (int nt = 0; nt < 16; ++nt) {
            uint32_t b[2];
            b[0] = ks[(nt * 8 + gid) * AP + k0 + tig];
            b[1] = ks[(nt * 8 + gid) * AP + k0 + tig + 4];
            mma8(sacc[nt], a, b);
        }
    }

    // ---- softmax over 128 cols (per row; rows gid and gid+8) ----
    const float scale = rsqrtf(128.f);
    float m0 = -1e30f, m1 = -1e30f;
    #pragma unroll
    for (int nt = 0; nt < 16; ++nt) {
        #pragma unroll
        for (int j = 0; j < 4; ++j) sacc[nt][j] *= scale;
        m0 = fmaxf(m0, fmaxf(sacc[nt][0], sacc[nt][1]));
        m1 = fmaxf(m1, fmaxf(sacc[nt][2], sacc[nt][3]));
    }
    m0 = fmaxf(m0, __shfl_xor_sync(0xffffffffu, m0, 1));
    m0 = fmaxf(m0, __shfl_xor_sync(0xffffffffu, m0, 2));
    m1 = fmaxf(m1, __shfl_xor_sync(0xffffffffu, m1, 1));
    m1 = fmaxf(m1, __shfl_xor_sync(0xffffffffu, m1, 2));

    float e0 = 0.f, e1 = 0.f;
    #pragma unroll
    for (int nt = 0; nt < 16; ++nt) {
        sacc[nt][0] = __expf(sacc[nt][0] - m0);
        sacc[nt][1] = __expf(sacc[nt][1] - m0);
        sacc[nt][2] = __expf(sacc[nt][2] - m1);
        sacc[nt][3] = __expf(sacc[nt][3] - m1);
        e0 += sacc[nt][0] + sacc[nt][1];
        e1 += sacc[nt][2] + sacc[nt][3];
    }
    e0 += __shfl_xor_sync(0xffffffffu, e0, 1);
    e0 += __shfl_xor_sync(0xffffffffu, e0, 2);
    e1 += __shfl_xor_sync(0xffffffffu, e1, 1);
    e1 += __shfl_xor_sync(0xffffffffu, e1, 2);
    const float i0 = 1.f / e0, i1 = 1.f / e1;

    // store P (tf32 bits) into warp's own Q region
    #pragma unroll
    for (int nt = 0; nt < 16; ++nt) {
        uint2 p0 = make_uint2(f2tf(sacc[nt][0] * i0), f2tf(sacc[nt][1] * i0));
        uint2 p1 = make_uint2(f2tf(sacc[nt][2] * i1), f2tf(sacc[nt][3] * i1));
        *(uint2*)(pw + gid * AP + nt * 8 + 2 * tig) = p0;
        *(uint2*)(pw + (gid + 8) * AP + nt * 8 + 2 * tig) = p1;
    }
    __syncwarp();

    // ---- O = P V ----
    float oacc[16][4];
    #pragma unroll
    for (int nt = 0; nt < 16; ++nt)
        #pragma unroll
        for (int j = 0; j < 4; ++j) oacc[nt][j] = 0.f;

    #pragma unroll
    for (int kt = 0; kt < 16; ++kt) {
        const int k0 = kt * 8;
        uint32_t a[4];
        a[0] = pw[gid * AP + k0 + tig];
        a[1] = pw[(gid + 8) * AP + k0 + tig];
        a[2] = pw[gid * AP + k0 + tig + 4];
        a[3] = pw[(gid + 8) * AP + k0 + tig + 4];
        #pragma unroll
        for (int nt = 0; nt < 16; ++nt) {
            uint32_t b[2];
            b[0] = vs[(k0 + tig) * AP + nt * 8 + gid];
            b[1] = vs[(k0 + tig + 4) * AP + nt * 8 + gid];
            mma8(oacc[nt], a, b);
        }
    }

    // ---- store out (fp32) ----
    float* op0 = out + base + (size_t)(warp * 16 + gid) * 128;
    float* op1 = op0 + 8 * 128;
    #pragma unroll
    for (int nt = 0; nt < 16; ++nt) {
        const int col = nt * 8 + 2 * tig;
        *(float2*)(op0 + col) = make_float2(oacc[nt][0], oacc[nt][1]);
        *(float2*)(op1 + col) = make_float2(oacc[nt][2], oacc[nt][3]);
    }
}

// ---------------------------------------------------------------------------
extern "C" void kernel_launch(void* const* d_in, const int* in_sizes, int n_in,
                              void* d_out, int out_size) {
    const float* x  = (const float*)d_in[0];
    const float* Wq = (const float*)d_in[1];
    const float* bq = (const float*)d_in[2];
    const float* Wk = (const float*)d_in[3];
    const float* bk = (const float*)d_in[4];
    const float* Wv = (const float*)d_in[5];
    const float* bv = (const float*)d_in[6];
    float* out = (float*)d_out;

    static bool attr_done = false;
    if (!attr_done) {
        cudaFuncSetAttribute(conv_kernel, cudaFuncAttributeMaxDynamicSharedMemorySize, CONV_SMEM);
        cudaFuncSetAttribute(attn_kernel, cudaFuncAttributeMaxDynamicSharedMemorySize, ATTN_SMEM);
        attr_done = true;
    }

    xcvt_kernel<<<16384, 512>>>((const float4*)x);
    wcvt_kernel<<<dim3(256, 3), 256>>>(Wq, Wk, Wv);

    conv_kernel<<<dim3(B_ * H_, 3), 512, CONV_SMEM>>>(bq, bk, bv);

    attn_kernel<<<B_ * C_, 256, ATTN_SMEM>>>(out);
}

// round 5
// speedup vs baseline: 7.0319x; 1.1520x over previous
#include <cuda_runtime.h>
#include <cstdint>
#include <math.h>

#define B_   16
#define C_   256
#define CIN  256
#define H_   128
#define W_   128
#define HW   (H_*W_)
#define TOT  ((size_t)B_*C_*HW)

// ---------------- device scratch (allocation-guard safe) -------------------
__device__ uint32_t g_q[TOT];                     // tf32 bits
__device__ uint32_t g_k[TOT];                     // tf32 bits
__device__ uint32_t g_v[TOT];                     // tf32 bits
__device__ uint32_t g_x32[(size_t)B_*CIN*HW];     // x as tf32 bits, NCHW
__device__ uint32_t g_wT[(size_t)3*9*256*256];    // [t][kk][ci][co] tf32 bits

// ---------------- helpers ---------------------------------------------------
__device__ __forceinline__ uint32_t smem_u32(const void* p) {
    uint32_t a;
    asm("{ .reg .u64 t; cvta.to.shared.u64 t, %1; cvt.u32.u64 %0, t; }" : "=r"(a) : "l"(p));
    return a;
}
__device__ __forceinline__ uint32_t f2tf(float f) {
    uint32_t r; asm("cvt.rna.tf32.f32 %0, %1;" : "=r"(r) : "f"(f)); return r;
}
__device__ __forceinline__ void cpa16(uint32_t d, const void* s) {
    asm volatile("cp.async.cg.shared.global [%0], [%1], 16;" :: "r"(d), "l"(s));
}
#define CP_COMMIT() asm volatile("cp.async.commit_group;" ::: "memory")
#define CP_WAIT1()  asm volatile("cp.async.wait_group 1;" ::: "memory")
#define CP_WAIT0()  asm volatile("cp.async.wait_group 0;" ::: "memory")

__device__ __forceinline__ void mma8(float* c, const uint32_t* a, const uint32_t* b) {
    asm volatile(
        "mma.sync.aligned.m16n8k8.row.col.f32.tf32.tf32.f32 "
        "{%0,%1,%2,%3}, {%4,%5,%6,%7}, {%8,%9}, {%0,%1,%2,%3};"
        : "+f"(c[0]), "+f"(c[1]), "+f"(c[2]), "+f"(c[3])
        : "r"(a[0]), "r"(a[1]), "r"(a[2]), "r"(a[3]), "r"(b[0]), "r"(b[1]));
}

// ---------------- prologue: convert x and W to tf32 bits --------------------
__global__ __launch_bounds__(512) void xcvt_kernel(const float4* __restrict__ x) {
    const size_t N4 = (size_t)B_ * CIN * HW / 4;
    uint4* dst = (uint4*)g_x32;
    for (size_t i = (size_t)blockIdx.x * blockDim.x + threadIdx.x; i < N4;
         i += (size_t)gridDim.x * blockDim.x) {
        float4 v = x[i];
        uint4 o;
        o.x = f2tf(v.x); o.y = f2tf(v.y); o.z = f2tf(v.z); o.w = f2tf(v.w);
        dst[i] = o;
    }
}

// W [co][ci][3][3] -> g_wT [t][kk][ci][co], tf32
__global__ __launch_bounds__(256) void wcvt_kernel(
    const float* __restrict__ Wq, const float* __restrict__ Wk, const float* __restrict__ Wv) {
    __shared__ float s[2304];
    const int co = blockIdx.x, t = blockIdx.y;
    const float* src = ((t == 0) ? Wq : (t == 1) ? Wk : Wv) + (size_t)co * 2304;
    for (int i = threadIdx.x; i < 2304; i += 256) s[i] = src[i];
    __syncthreads();
    const int ci = threadIdx.x;
    uint32_t* dst = g_wT + (size_t)t * 9 * 65536;
    #pragma unroll
    for (int kk = 0; kk < 9; ++kk)
        dst[((size_t)kk * 256 + ci) * 256 + co] = f2tf(s[ci * 9 + kk]);
}

// ---------------- conv: implicit GEMM on mma.sync tf32 ----------------------
// chunk it = (khIdx, ci8, kw), kw fastest. A refilled every chunk (3-ring);
// B (x row with halo) refilled only when kw==0 (3-ring), reads shifted by kw-1.
#define SA_STRIDE 264
#define SB_STRIDE 136                      // halo layout: word 4+w for wsrc w
#define SA_WORDS  (32 * SA_STRIDE)         // 8448
#define SB_WORDS  (32 * SB_STRIDE)         // 4352
#define SB_BASE   (3 * SA_WORDS)
#define CONV_SMEM ((3 * SA_WORDS + 3 * SB_WORDS) * 4)   // 153600 B

__global__ __launch_bounds__(512, 1) void conv_kernel(
    const float* __restrict__ bq, const float* __restrict__ bk, const float* __restrict__ bv) {
    extern __shared__ uint32_t sm[];
    const int tid = threadIdx.x, lane = tid & 31, warp = tid >> 5;
    const int gid = lane >> 2, tig = lane & 3;
    const int cob = (warp >> 2) * 64, nb = (warp & 3) * 32;
    const int bh = blockIdx.x, t = blockIdx.y;
    const int b = bh >> 7, h = bh & 127;
    const int kh0 = (h == 0) ? 1 : 0;
    const int kh1 = (h == 127) ? 1 : 2;
    const int nch = (kh1 - kh0 + 1) * 24;   // (kh)(ci8)(kw) chunks
    const uint32_t smbase = smem_u32(sm);

    // zero the constant halo columns (words 3 and 132) of all 3 B stages
    if (tid < 192) {
        const int s = tid / 64, k = (tid % 64) >> 1, e = tid & 1;
        sm[SB_BASE + s * SB_WORDS + k * SB_STRIDE + (e ? 132 : 3)] = 0u;
    }

    float acc[4][4][4];
    #pragma unroll
    for (int i = 0; i < 4; ++i)
        #pragma unroll
        for (int j = 0; j < 4; ++j)
            #pragma unroll
            for (int l = 0; l < 4; ++l) acc[i][j][l] = 0.f;

    auto fill = [&](int it) {
        const int kh = kh0 + it / 24;
        const int rem = it % 24;
        const int ci8 = rem / 3, kw = rem % 3;
        // A: weights [t][kh*3+kw][ci-chunk][co]
        const uint32_t* wp = g_wT + (((size_t)t * 9 + kh * 3 + kw) * 256 + ci8 * 32) * 256;
        const uint32_t dA = smbase + ((it % 3) * SA_WORDS) * 4;
        #pragma unroll
        for (int i = 0; i < 4; ++i) {
            const int idx = tid + i * 512;
            const int k = idx >> 6, co4 = (idx & 63) << 2;
            cpa16(dA + (uint32_t)(k * SA_STRIDE + co4) * 4, wp + k * 256 + co4);
        }
        // B: x row (full 128 px, no shift) — only when kw == 0
        if (kw == 0) {
            const int hsrc = h + kh - 1;
            const uint32_t* xp = g_x32 + (((size_t)b * 256 + ci8 * 32) * 128 + hsrc) * 128;
            const uint32_t dB = smbase + (SB_BASE + ((it / 3) % 3) * SB_WORDS) * 4;
            #pragma unroll
            for (int i = 0; i < 2; ++i) {
                const int idx = tid + i * 512;
                const int k = idx >> 5, c4 = (idx & 31) << 2;
                cpa16(dB + (uint32_t)(k * SB_STRIDE + 4 + c4) * 4, xp + (size_t)k * HW + c4);
            }
        }
    };

    auto compute = [&](int it) {
        const int kw = it % 3;
        const uint32_t* A = sm + (it % 3) * SA_WORDS;
        const uint32_t* Bp = sm + SB_BASE + ((it / 3) % 3) * SB_WORDS + 3 + kw;  // word 4+(kw-1)
        #pragma unroll
        for (int ks = 0; ks < 4; ++ks) {
            const int k0 = ks * 8;
            uint32_t af[4][4], bf[4][2];
            #pragma unroll
            for (int mi = 0; mi < 4; ++mi) {
                const int base = (k0 + tig) * SA_STRIDE + cob + mi * 16 + gid;
                af[mi][0] = A[base];
                af[mi][1] = A[base + 8];
                af[mi][2] = A[base + 4 * SA_STRIDE];
                af[mi][3] = A[base + 4 * SA_STRIDE + 8];
            }
            #pragma unroll
            for (int ni = 0; ni < 4; ++ni) {
                const int base = (k0 + tig) * SB_STRIDE + nb + ni * 8 + gid;
                bf[ni][0] = Bp[base];
                bf[ni][1] = Bp[base + 4 * SB_STRIDE];
            }
            #pragma unroll
            for (int mi = 0; mi < 4; ++mi)
                #pragma unroll
                for (int ni = 0; ni < 4; ++ni)
                    mma8(acc[mi][ni], af[mi], bf[ni]);
        }
    };

    fill(0); CP_COMMIT();
    fill(1); CP_COMMIT();
    for (int it = 0; it < nch; ++it) {
        CP_WAIT1();
        __syncthreads();
        compute(it);
        if (it + 2 < nch) fill(it + 2);
        CP_COMMIT();
    }

    // epilogue: bias + store as tf32 bits
    uint32_t* outp = (t == 0) ? g_q : (t == 1) ? g_k : g_v;
    const float* bias = (t == 0) ? bq : (t == 1) ? bk : bv;
    #pragma unroll
    for (int mi = 0; mi < 4; ++mi) {
        const int co0 = cob + mi * 16 + gid;
        const float bv0 = bias[co0], bv1 = bias[co0 + 8];
        uint32_t* r0 = outp + (((size_t)b * C_ + co0) * H_ + h) * W_;
        uint32_t* r1 = r0 + (size_t)8 * HW;
        #pragma unroll
        for (int ni = 0; ni < 4; ++ni) {
            const int col = nb + ni * 8 + 2 * tig;
            uint2 v0 = make_uint2(f2tf(acc[mi][ni][0] + bv0), f2tf(acc[mi][ni][1] + bv0));
            uint2 v1 = make_uint2(f2tf(acc[mi][ni][2] + bv1), f2tf(acc[mi][ni][3] + bv1));
            *(uint2*)(r0 + col) = v0;
            *(uint2*)(r1 + col) = v1;
        }
    }
}

// ---------------- attention: tensor-core tf32, V-load overlapped ------------
#define AP 132
#define ATTN_SMEM (3 * 128 * AP * 4)   // 202752 B

__global__ __launch_bounds__(256, 1) void attn_kernel(float* __restrict__ out) {
    extern __shared__ uint32_t asm_[];
    uint32_t* qs = asm_;
    uint32_t* ks = qs + 128 * AP;
    uint32_t* vs = ks + 128 * AP;

    const int bc = blockIdx.x;
    const size_t base = (size_t)bc * HW;
    const int tid = threadIdx.x;
    const int lane = tid & 31;
    const int warp = tid >> 5;
    const int gid = lane >> 2, tig = lane & 3;
    const uint32_t smbase = smem_u32(asm_);

    // group 0: Q + K
    for (int i = tid; i < 4096; i += 256) {
        const int r = i >> 5, c4 = i & 31;
        const uint32_t doff = (uint32_t)(r * AP + c4 * 4) * 4;
        const size_t goff = base + (size_t)r * 128 + c4 * 4;
        cpa16(smbase + doff,                g_q + goff);
        cpa16(smbase + 128 * AP * 4 + doff, g_k + goff);
    }
    CP_COMMIT();
    // group 1: V (overlaps S-GEMM + softmax)
    for (int i = tid; i < 4096; i += 256) {
        const int r = i >> 5, c4 = i & 31;
        cpa16(smbase + 2 * 128 * AP * 4 + (uint32_t)(r * AP + c4 * 4) * 4,
              g_v + base + (size_t)r * 128 + c4 * 4);
    }
    CP_COMMIT();
    CP_WAIT1();
    __syncthreads();

    const uint32_t* qw = qs + warp * 16 * AP;
    uint32_t* pw = qs + warp * 16 * AP;

    // ---- S = Q K^T ----
    float sacc[16][4];
    #pragma unroll
    for (int nt = 0; nt < 16; ++nt)
        #pragma unroll
        for (int j = 0; j < 4; ++j) sacc[nt][j] = 0.f;

    #pragma unroll
    for (int kt = 0; kt < 16; ++kt) {
        const int k0 = kt * 8;
        uint32_t a[4];
        a[0] = qw[gid * AP + k0 + tig];
        a[1] = qw[(gid + 8) * AP + k0 + tig];
        a[2] = qw[gid * AP + k0 + tig + 4];
        a[3] = qw[(gid + 8) * AP + k0 + tig + 4];
        #pragma unroll
        for (int nt = 0; nt < 16; ++nt) {
            uint32_t b[2];
            b[0] = ks[(nt * 8 + gid) * AP + k0 + tig];
            b[1] = ks[(nt * 8 + gid) * AP + k0 + tig + 4];
            mma8(sacc[nt], a, b);
        }
    }

    // ---- softmax ----
    const float scale = rsqrtf(128.f);
    float m0 = -1e30f, m1 = -1e30f;
    #pragma unroll
    for (int nt = 0; nt < 16; ++nt) {
        #pragma unroll
        for (int j = 0; j < 4; ++j) sacc[nt][j] *= scale;
        m0 = fmaxf(m0, fmaxf(sacc[nt][0], sacc[nt][1]));
        m1 = fmaxf(m1, fmaxf(sacc[nt][2], sacc[nt][3]));
    }
    m0 = fmaxf(m0, __shfl_xor_sync(0xffffffffu, m0, 1));
    m0 = fmaxf(m0, __shfl_xor_sync(0xffffffffu, m0, 2));
    m1 = fmaxf(m1, __shfl_xor_sync(0xffffffffu, m1, 1));
    m1 = fmaxf(m1, __shfl_xor_sync(0xffffffffu, m1, 2));

    float e0 = 0.f, e1 = 0.f;
    #pragma unroll
    for (int nt = 0; nt < 16; ++nt) {
        sacc[nt][0] = __expf(sacc[nt][0] - m0);
        sacc[nt][1] = __expf(sacc[nt][1] - m0);
        sacc[nt][2] = __expf(sacc[nt][2] - m1);
        sacc[nt][3] = __expf(sacc[nt][3] - m1);
        e0 += sacc[nt][0] + sacc[nt][1];
        e1 += sacc[nt][2] + sacc[nt][3];
    }
    e0 += __shfl_xor_sync(0xffffffffu, e0, 1);
    e0 += __shfl_xor_sync(0xffffffffu, e0, 2);
    e1 += __shfl_xor_sync(0xffffffffu, e1, 1);
    e1 += __shfl_xor_sync(0xffffffffu, e1, 2);
    const float i0 = 1.f / e0, i1 = 1.f / e1;

    #pragma unroll
    for (int nt = 0; nt < 16; ++nt) {
        uint2 p0 = make_uint2(f2tf(sacc[nt][0] * i0), f2tf(sacc[nt][1] * i0));
        uint2 p1 = make_uint2(f2tf(sacc[nt][2] * i1), f2tf(sacc[nt][3] * i1));
        *(uint2*)(pw + gid * AP + nt * 8 + 2 * tig) = p0;
        *(uint2*)(pw + (gid + 8) * AP + nt * 8 + 2 * tig) = p1;
    }
    __syncwarp();

    CP_WAIT0();        // V landed (own copies); barrier makes all copies visible
    __syncthreads();

    // ---- O = P V ----
    float oacc[16][4];
    #pragma unroll
    for (int nt = 0; nt < 16; ++nt)
        #pragma unroll
        for (int j = 0; j < 4; ++j) oacc[nt][j] = 0.f;

    #pragma unroll
    for (int kt = 0; kt < 16; ++kt) {
        const int k0 = kt * 8;
        uint32_t a[4];
        a[0] = pw[gid * AP + k0 + tig];
        a[1] = pw[(gid + 8) * AP + k0 + tig];
        a[2] = pw[gid * AP + k0 + tig + 4];
        a[3] = pw[(gid + 8) * AP + k0 + tig + 4];
        #pragma unroll
        for (int nt = 0; nt < 16; ++nt) {
            uint32_t b[2];
            b[0] = vs[(k0 + tig) * AP + nt * 8 + gid];
            b[1] = vs[(k0 + tig + 4) * AP + nt * 8 + gid];
            mma8(oacc[nt], a, b);
        }
    }

    float* op0 = out + base + (size_t)(warp * 16 + gid) * 128;
    float* op1 = op0 + 8 * 128;
    #pragma unroll
    for (int nt = 0; nt < 16; ++nt) {
        const int col = nt * 8 + 2 * tig;
        *(float2*)(op0 + col) = make_float2(oacc[nt][0], oacc[nt][1]);
        *(float2*)(op1 + col) = make_float2(oacc[nt][2], oacc[nt][3]);
    }
}

// ---------------------------------------------------------------------------
extern "C" void kernel_launch(void* const* d_in, const int* in_sizes, int n_in,
                              void* d_out, int out_size) {
    const float* x  = (const float*)d_in[0];
    const float* Wq = (const float*)d_in[1];
    const float* bq = (const float*)d_in[2];
    const float* Wk = (const float*)d_in[3];
    const float* bk = (const float*)d_in[4];
    const float* Wv = (const float*)d_in[5];
    const float* bv = (const float*)d_in[6];
    float* out = (float*)d_out;

    static bool attr_done = false;
    if (!attr_done) {
        cudaFuncSetAttribute(conv_kernel, cudaFuncAttributeMaxDynamicSharedMemorySize, CONV_SMEM);
        cudaFuncSetAttribute(attn_kernel, cudaFuncAttributeMaxDynamicSharedMemorySize, ATTN_SMEM);
        attr_done = true;
    }

    xcvt_kernel<<<16384, 512>>>((const float4*)x);
    wcvt_kernel<<<dim3(256, 3), 256>>>(Wq, Wk, Wv);

    conv_kernel<<<dim3(B_ * H_, 3), 512, CONV_SMEM>>>(bq, bk, bv);

    attn_kernel<<<B_ * C_, 256, ATTN_SMEM>>>(out);
}